// round 2
// baseline (speedup 1.0000x reference)
#include <cuda_runtime.h>
#include <cuda_bf16.h>
#include <cstdint>
#include <cstddef>

constexpr int S_BS = 8, S_SEQ = 512, S_DIM = 768, S_NP = 32, S_PE = 200;
constexpr int S_L = 20, S_EMB = 128, S_VOCAB = 30522;
constexpr int S_BP = S_BS * S_NP;            // 256
constexpr int S_ROWS = S_BP * S_L;           // 5120
constexpr int S_DIN2 = 2 * S_DIM;            // 1536

// ---------------- scratch ----------------
constexpr size_t SZ_A1   = (size_t)S_BP * S_DIN2 * 2;      // bf16
constexpr size_t SZ_W1T  = (size_t)S_DIM * S_DIN2 * 2;
constexpr size_t SZ_W2T  = (size_t)S_DIM * S_DIM * 2;
constexpr size_t SZ_WPT  = (size_t)S_EMB * S_DIM * 2;
constexpr size_t SZ_WD   = (size_t)S_VOCAB * S_EMB * 2;
constexpr size_t SZ_P    = (size_t)S_BP * S_DIM * 4;       // f32
constexpr size_t SZ_POSP = (size_t)S_L * S_DIM * 4;
constexpr size_t SZ_H1   = (size_t)S_ROWS * S_DIM * 2;
constexpr size_t SZ_PRE2 = (size_t)S_ROWS * S_DIM * 4;
constexpr size_t SZ_H3   = (size_t)S_ROWS * S_EMB * 2;

constexpr size_t OFF_A1H  = 0;
constexpr size_t OFF_A1L  = OFF_A1H  + SZ_A1;
constexpr size_t OFF_W1TH = OFF_A1L  + SZ_A1;
constexpr size_t OFF_W1TL = OFF_W1TH + SZ_W1T;
constexpr size_t OFF_W2TH = OFF_W1TL + SZ_W1T;
constexpr size_t OFF_W2TL = OFF_W2TH + SZ_W2T;
constexpr size_t OFF_WPTH = OFF_W2TL + SZ_W2T;
constexpr size_t OFF_WPTL = OFF_WPTH + SZ_WPT;
constexpr size_t OFF_WDH  = OFF_WPTL + SZ_WPT;
constexpr size_t OFF_WDL  = OFF_WDH  + SZ_WD;
constexpr size_t OFF_P    = OFF_WDL  + SZ_WD;
constexpr size_t OFF_POSP = OFF_P    + SZ_P;
constexpr size_t OFF_H1H  = OFF_POSP + SZ_POSP;
constexpr size_t OFF_H1L  = OFF_H1H  + SZ_H1;
constexpr size_t OFF_PRE2 = OFF_H1L  + SZ_H1;
constexpr size_t OFF_H2H  = OFF_PRE2 + SZ_PRE2;
constexpr size_t OFF_H2L  = OFF_H2H  + SZ_H1;
constexpr size_t OFF_H3H  = OFF_H2L  + SZ_H1;
constexpr size_t OFF_H3L  = OFF_H3H  + SZ_H3;
constexpr size_t SCRATCH_BYTES = OFF_H3L + SZ_H3;

__device__ __align__(1024) unsigned char g_scratch[SCRATCH_BYTES];

// ---------------- helpers ----------------
__device__ __forceinline__ void split2(float v, __nv_bfloat16& hi, __nv_bfloat16& lo) {
    __nv_bfloat16 h = __float2bfloat16(v);
    hi = h;
    lo = __float2bfloat16(v - __bfloat162float(h));
}

__device__ __forceinline__ float gelu_exact(float x) {
    return 0.5f * x * (1.0f + erff(x * 0.70710678118654752440f));
}

#define MMA_BF16(c, a, b)                                                     \
    asm volatile(                                                             \
        "mma.sync.aligned.m16n8k16.row.col.f32.bf16.bf16.f32 "                \
        "{%0,%1,%2,%3},{%4,%5,%6,%7},{%8,%9},{%0,%1,%2,%3};\n"                \
        : "+f"((c)[0]), "+f"((c)[1]), "+f"((c)[2]), "+f"((c)[3])              \
        : "r"((a)[0]), "r"((a)[1]), "r"((a)[2]), "r"((a)[3]),                 \
          "r"((b)[0]), "r"((b)[1]))

// ---------------- prep kernels ----------------
__global__ void gather_split_kernel(const float* __restrict__ hidden,
                                    const int* __restrict__ pairs,
                                    __nv_bfloat16* __restrict__ Ah,
                                    __nv_bfloat16* __restrict__ Al) {
    int id = blockIdx.x * 256 + threadIdx.x;      // 256*1536
    int bp = id / S_DIN2;
    int k  = id - bp * S_DIN2;
    int side = (k >= S_DIM) ? 1 : 0;
    int col  = k - side * S_DIM;
    int s = pairs[bp * 2 + side];
    int b = bp >> 5;
    float v = hidden[((size_t)(b * S_SEQ + s)) * S_DIM + col];
    split2(v, Ah[id], Al[id]);
}

// W fp32 [K][N] -> Th/Tl bf16 [N][K]
__global__ void transpose_split_kernel(const float* __restrict__ W, int K, int N,
                                       __nv_bfloat16* __restrict__ Th,
                                       __nv_bfloat16* __restrict__ Tl) {
    __shared__ float tile[32][33];
    int k0 = blockIdx.y * 32, n0 = blockIdx.x * 32;
    #pragma unroll
    for (int i = 0; i < 4; i++) {
        int kk = threadIdx.y + i * 8;
        tile[kk][threadIdx.x] = W[(size_t)(k0 + kk) * N + n0 + threadIdx.x];
    }
    __syncthreads();
    #pragma unroll
    for (int i = 0; i < 4; i++) {
        int nn = threadIdx.y + i * 8;
        float v = tile[threadIdx.x][nn];
        size_t o = (size_t)(n0 + nn) * K + k0 + threadIdx.x;
        split2(v, Th[o], Tl[o]);
    }
}

__global__ void copy_split_kernel(const float* __restrict__ src,
                                  __nv_bfloat16* __restrict__ h,
                                  __nv_bfloat16* __restrict__ l, int n) {
    int id = blockIdx.x * 256 + threadIdx.x;
    if (id < n) split2(src[id], h[id], l[id]);
}

// PosP[l][n] = sum_k pos_emb[l][k] * W1[1536+k][n]   (fp32, tiny)
__global__ void posmat_kernel(const float* __restrict__ pos_emb,
                              const float* __restrict__ W1,
                              float* __restrict__ PosP) {
    __shared__ float sp[S_PE];
    int l = blockIdx.x;
    if (threadIdx.x < S_PE) sp[threadIdx.x] = pos_emb[l * S_PE + threadIdx.x];
    __syncthreads();
    int n = threadIdx.x;
    float a = 0.f;
    #pragma unroll 4
    for (int k = 0; k < S_PE; k++)
        a += sp[k] * W1[(size_t)(S_DIN2 + k) * S_DIM + n];
    PosP[l * S_DIM + n] = a;
}

// ---------------- unified split-bf16 GEMM ----------------
// C[M,N] = A[M,K] @ Bt[N,K]^T (+bias). 3 terms: AhBh+AhBl+AlBh.
// Block tile 128x128x32, 8 warps (2x4), warp 64x32. M%128==0, K%32==0.
constexpr int G_STR  = 20;                // words per 32-elem k-row (16 data + 4 pad)
constexpr int G_MATW = 128 * G_STR;
constexpr int GEMM_SMEM = 2 * 4 * G_MATW * 4;  // 81920 B

__global__ __launch_bounds__(256, 1)
void gemm_bb_kernel(int M, int N, int K,
                    const __nv_bfloat16* __restrict__ Ahp, const __nv_bfloat16* __restrict__ Alp,
                    const __nv_bfloat16* __restrict__ Bhp, const __nv_bfloat16* __restrict__ Blp,
                    const float* __restrict__ bias,
                    float* __restrict__ Cf,
                    __nv_bfloat16* __restrict__ Ch, __nv_bfloat16* __restrict__ Cl) {
    extern __shared__ uint32_t sm[];
    const int tid  = threadIdx.x;
    const int lane = tid & 31, warp = tid >> 5;
    const int wr = warp >> 2, wc = warp & 3;
    const int g = lane >> 2, tg = lane & 3;
    const int m0 = wr * 64, n0 = wc * 32;
    const int am0 = blockIdx.x * 128;
    const int bn0 = blockIdx.y * 128;
    const int Kw = K >> 1;
    const uint32_t* gA0 = (const uint32_t*)Ahp;
    const uint32_t* gA1 = (const uint32_t*)Alp;
    const uint32_t* gB0 = (const uint32_t*)Bhp;
    const uint32_t* gB1 = (const uint32_t*)Blp;
    const uint32_t smbase = (uint32_t)__cvta_generic_to_shared(sm);

    float acc[4][4][4];
    #pragma unroll
    for (int a = 0; a < 4; a++)
        #pragma unroll
        for (int b = 0; b < 4; b++)
            #pragma unroll
            for (int c = 0; c < 4; c++) acc[a][b][c] = 0.f;

    const int nk = K >> 5;

    auto load_stage = [&](int kt, int s) {
        const int kw0 = kt * 16;
        const uint32_t sb = smbase + (uint32_t)(s * 4 * G_MATW) * 4u;
        #pragma unroll
        for (int i = 0; i < 8; i++) {
            int idx = tid + i * 256;
            int row = idx >> 4, w = idx & 15;
            uint32_t sa = sb + (uint32_t)(row * G_STR + w) * 4u;
            long gi = (long)(am0 + row) * Kw + kw0 + w;
            asm volatile("cp.async.ca.shared.global [%0], [%1], 4;\n"
                         :: "r"(sa), "l"(gA0 + gi));
            asm volatile("cp.async.ca.shared.global [%0], [%1], 4;\n"
                         :: "r"(sa + (uint32_t)G_MATW * 4u), "l"(gA1 + gi));
            int nr = bn0 + row;
            int ok = (nr < N) ? 4 : 0;
            long gj = (long)(nr < N ? nr : 0) * Kw + kw0 + w;
            asm volatile("cp.async.ca.shared.global [%0], [%1], 4, %2;\n"
                         :: "r"(sa + 2u * (uint32_t)G_MATW * 4u), "l"(gB0 + gj), "r"(ok));
            asm volatile("cp.async.ca.shared.global [%0], [%1], 4, %2;\n"
                         :: "r"(sa + 3u * (uint32_t)G_MATW * 4u), "l"(gB1 + gj), "r"(ok));
        }
        asm volatile("cp.async.commit_group;\n");
    };

    load_stage(0, 0);
    for (int kt = 0; kt < nk; kt++) {
        int s = kt & 1;
        if (kt + 1 < nk) {
            load_stage(kt + 1, s ^ 1);
            asm volatile("cp.async.wait_group 1;\n");
        } else {
            asm volatile("cp.async.wait_group 0;\n");
        }
        __syncthreads();

        const uint32_t* SA0 = sm + s * 4 * G_MATW;
        const uint32_t* SA1 = SA0 + G_MATW;
        const uint32_t* SB0 = SA0 + 2 * G_MATW;
        const uint32_t* SB1 = SA0 + 3 * G_MATW;

        #pragma unroll
        for (int ks = 0; ks < 2; ks++) {
            const int w0 = ks * 8;
            uint32_t ah[4][4], al[4][4], bh[4][2], bl[4][2];
            #pragma unroll
            for (int mi = 0; mi < 4; mi++) {
                int o = (m0 + mi * 16 + g) * G_STR + w0 + tg;
                ah[mi][0] = SA0[o];              ah[mi][1] = SA0[o + 8 * G_STR];
                ah[mi][2] = SA0[o + 4];          ah[mi][3] = SA0[o + 8 * G_STR + 4];
                al[mi][0] = SA1[o];              al[mi][1] = SA1[o + 8 * G_STR];
                al[mi][2] = SA1[o + 4];          al[mi][3] = SA1[o + 8 * G_STR + 4];
            }
            #pragma unroll
            for (int nj = 0; nj < 4; nj++) {
                int o = (n0 + nj * 8 + g) * G_STR + w0 + tg;
                bh[nj][0] = SB0[o]; bh[nj][1] = SB0[o + 4];
                bl[nj][0] = SB1[o]; bl[nj][1] = SB1[o + 4];
            }
            #pragma unroll
            for (int mi = 0; mi < 4; mi++)
                #pragma unroll
                for (int nj = 0; nj < 4; nj++) {
                    MMA_BF16(acc[mi][nj], ah[mi], bh[nj]);
                    MMA_BF16(acc[mi][nj], ah[mi], bl[nj]);
                    MMA_BF16(acc[mi][nj], al[mi], bh[nj]);
                }
        }
        __syncthreads();
    }

    #pragma unroll
    for (int mi = 0; mi < 4; mi++) {
        int r0 = am0 + m0 + mi * 16 + g;
        size_t base0 = (size_t)r0 * N;
        size_t base1 = (size_t)(r0 + 8) * N;
        #pragma unroll
        for (int nj = 0; nj < 4; nj++) {
            int c0 = bn0 + n0 + nj * 8 + tg * 2;
            float v0 = acc[mi][nj][0], v1 = acc[mi][nj][1];
            float v2 = acc[mi][nj][2], v3 = acc[mi][nj][3];
            if (bias) {
                float bb0 = (c0 < N) ? bias[c0] : 0.f;
                float bb1 = (c0 + 1 < N) ? bias[c0 + 1] : 0.f;
                v0 += bb0; v1 += bb1; v2 += bb0; v3 += bb1;
            }
            if (Cf) {
                if (c0 < N)     { Cf[base0 + c0]     = v0; Cf[base1 + c0]     = v2; }
                if (c0 + 1 < N) { Cf[base0 + c0 + 1] = v1; Cf[base1 + c0 + 1] = v3; }
            } else {
                if (c0 < N) {
                    split2(v0, Ch[base0 + c0],     Cl[base0 + c0]);
                    split2(v2, Ch[base1 + c0],     Cl[base1 + c0]);
                }
                if (c0 + 1 < N) {
                    split2(v1, Ch[base0 + c0 + 1], Cl[base0 + c0 + 1]);
                    split2(v3, Ch[base1 + c0 + 1], Cl[base1 + c0 + 1]);
                }
            }
        }
    }
}

// ---------------- gelu + LN (one 768-row per 256-thread block) ----------------
__device__ __forceinline__ void ln_write(float v0, float v1, float v2, int r,
                                         const float* __restrict__ gam,
                                         const float* __restrict__ bet,
                                         __nv_bfloat16* __restrict__ Hh,
                                         __nv_bfloat16* __restrict__ Hl,
                                         float* red) {
    int t = threadIdx.x;
    float s1 = v0 + v1 + v2;
    float s2 = v0 * v0 + v1 * v1 + v2 * v2;
    #pragma unroll
    for (int o = 16; o; o >>= 1) {
        s1 += __shfl_xor_sync(0xffffffffu, s1, o);
        s2 += __shfl_xor_sync(0xffffffffu, s2, o);
    }
    if ((t & 31) == 0) { red[t >> 5] = s1; red[8 + (t >> 5)] = s2; }
    __syncthreads();
    s1 = 0.f; s2 = 0.f;
    #pragma unroll
    for (int i = 0; i < 8; i++) { s1 += red[i]; s2 += red[8 + i]; }
    float mean = s1 * (1.0f / S_DIM);
    float var  = s2 * (1.0f / S_DIM) - mean * mean;
    float rstd = rsqrtf(fmaxf(var, 0.0f) + 1e-12f);
    size_t rb = (size_t)r * S_DIM;
    float v[3] = {v0, v1, v2};
    #pragma unroll
    for (int j = 0; j < 3; j++) {
        int c = t + j * 256;
        float y = (v[j] - mean) * rstd * gam[c] + bet[c];
        split2(y, Hh[rb + c], Hl[rb + c]);
    }
}

__global__ void expand_act_kernel(const float* __restrict__ P,
                                  const float* __restrict__ PosP,
                                  const float* __restrict__ b1,
                                  const float* __restrict__ g1,
                                  const float* __restrict__ be1,
                                  __nv_bfloat16* __restrict__ Hh,
                                  __nv_bfloat16* __restrict__ Hl) {
    __shared__ float red[16];
    int r = blockIdx.x;
    int bp = r / S_L, l = r - bp * S_L;
    int t = threadIdx.x;
    float v[3];
    #pragma unroll
    for (int j = 0; j < 3; j++) {
        int c = t + j * 256;
        float pre = P[bp * S_DIM + c] + PosP[l * S_DIM + c] + b1[c];
        v[j] = gelu_exact(pre);
    }
    ln_write(v[0], v[1], v[2], r, g1, be1, Hh, Hl, red);
}

__global__ void act2_kernel(const float* __restrict__ X,
                            const float* __restrict__ g2,
                            const float* __restrict__ be2,
                            __nv_bfloat16* __restrict__ Hh,
                            __nv_bfloat16* __restrict__ Hl) {
    __shared__ float red[16];
    int r = blockIdx.x;
    int t = threadIdx.x;
    size_t rb = (size_t)r * S_DIM;
    float v[3];
    #pragma unroll
    for (int j = 0; j < 3; j++) {
        int c = t + j * 256;
        v[j] = gelu_exact(X[rb + c]);
    }
    ln_write(v[0], v[1], v[2], r, g2, be2, Hh, Hl, red);
}

// ---------------- launch ----------------
extern "C" void kernel_launch(void* const* d_in, const int* in_sizes, int n_in,
                              void* d_out, int out_size) {
    (void)in_sizes; (void)n_in; (void)out_size;
    const float* hidden  = (const float*)d_in[0];
    const int*   pairs   = (const int*)d_in[1];
    const float* pos_emb = (const float*)d_in[2];
    const float* W1      = (const float*)d_in[3];
    const float* b1      = (const float*)d_in[4];
    const float* g1      = (const float*)d_in[5];
    const float* be1     = (const float*)d_in[6];
    const float* W2      = (const float*)d_in[7];
    const float* b2      = (const float*)d_in[8];
    const float* g2      = (const float*)d_in[9];
    const float* be2     = (const float*)d_in[10];
    const float* Wp      = (const float*)d_in[11];
    const float* bpv     = (const float*)d_in[12];
    const float* Wdec    = (const float*)d_in[13];
    float* out = (float*)d_out;

    void* sp = nullptr;
    cudaGetSymbolAddress(&sp, g_scratch);
    char* S = (char*)sp;
    __nv_bfloat16* A1h  = (__nv_bfloat16*)(S + OFF_A1H);
    __nv_bfloat16* A1l  = (__nv_bfloat16*)(S + OFF_A1L);
    __nv_bfloat16* W1th = (__nv_bfloat16*)(S + OFF_W1TH);
    __nv_bfloat16* W1tl = (__nv_bfloat16*)(S + OFF_W1TL);
    __nv_bfloat16* W2th = (__nv_bfloat16*)(S + OFF_W2TH);
    __nv_bfloat16* W2tl = (__nv_bfloat16*)(S + OFF_W2TL);
    __nv_bfloat16* Wpth = (__nv_bfloat16*)(S + OFF_WPTH);
    __nv_bfloat16* Wptl = (__nv_bfloat16*)(S + OFF_WPTL);
    __nv_bfloat16* Wdh  = (__nv_bfloat16*)(S + OFF_WDH);
    __nv_bfloat16* Wdl  = (__nv_bfloat16*)(S + OFF_WDL);
    float* P    = (float*)(S + OFF_P);
    float* PosP = (float*)(S + OFF_POSP);
    __nv_bfloat16* h1h = (__nv_bfloat16*)(S + OFF_H1H);
    __nv_bfloat16* h1l = (__nv_bfloat16*)(S + OFF_H1L);
    float* pre2 = (float*)(S + OFF_PRE2);
    __nv_bfloat16* h2h = (__nv_bfloat16*)(S + OFF_H2H);
    __nv_bfloat16* h2l = (__nv_bfloat16*)(S + OFF_H2L);
    __nv_bfloat16* h3h = (__nv_bfloat16*)(S + OFF_H3H);
    __nv_bfloat16* h3l = (__nv_bfloat16*)(S + OFF_H3L);

    cudaFuncSetAttribute(gemm_bb_kernel,
                         cudaFuncAttributeMaxDynamicSharedMemorySize, GEMM_SMEM);

    // prep
    gather_split_kernel<<<(S_BP * S_DIN2) / 256, 256>>>(hidden, pairs, A1h, A1l);
    transpose_split_kernel<<<dim3(S_DIM / 32, S_DIN2 / 32), dim3(32, 8)>>>(W1, S_DIN2, S_DIM, W1th, W1tl);
    transpose_split_kernel<<<dim3(S_DIM / 32, S_DIM / 32), dim3(32, 8)>>>(W2, S_DIM, S_DIM, W2th, W2tl);
    transpose_split_kernel<<<dim3(S_EMB / 32, S_DIM / 32), dim3(32, 8)>>>(Wp, S_DIM, S_EMB, Wpth, Wptl);
    copy_split_kernel<<<(S_VOCAB * S_EMB + 255) / 256, 256>>>(Wdec, Wdh, Wdl, S_VOCAB * S_EMB);
    posmat_kernel<<<S_L, S_DIM>>>(pos_emb, W1, PosP);

    // GEMM1: P[256,768] = Acat[256,1536] @ W1t^T   (no bias; b1 added in expand)
    gemm_bb_kernel<<<dim3(S_BP / 128, S_DIM / 128), 256, GEMM_SMEM>>>(
        S_BP, S_DIM, S_DIN2, A1h, A1l, W1th, W1tl,
        nullptr, P, nullptr, nullptr);

    // expand over L + gelu + LN1 -> h1 (split)
    expand_act_kernel<<<S_ROWS, 256>>>(P, PosP, b1, g1, be1, h1h, h1l);

    // GEMM2: pre2[5120,768] = h1 @ W2t^T + b2
    gemm_bb_kernel<<<dim3(S_ROWS / 128, S_DIM / 128), 256, GEMM_SMEM>>>(
        S_ROWS, S_DIM, S_DIM, h1h, h1l, W2th, W2tl,
        b2, pre2, nullptr, nullptr);

    // gelu + LN2 -> h2 (split)
    act2_kernel<<<S_ROWS, 256>>>(pre2, g2, be2, h2h, h2l);

    // GEMM3: h3[5120,128] = h2 @ Wpt^T + bp  (split output)
    gemm_bb_kernel<<<dim3(S_ROWS / 128, 1), 256, GEMM_SMEM>>>(
        S_ROWS, S_EMB, S_DIM, h2h, h2l, Wpth, Wptl,
        bpv, nullptr, h3h, h3l);

    // GEMM4: out[5120,30522] = h3 @ Wdec^T
    gemm_bb_kernel<<<dim3(S_ROWS / 128, (S_VOCAB + 127) / 128), 256, GEMM_SMEM>>>(
        S_ROWS, S_VOCAB, S_EMB, h3h, h3l, Wdh, Wdl,
        nullptr, out, nullptr, nullptr);
}

// round 4
// speedup vs baseline: 1.8804x; 1.8804x over previous
#include <cuda_runtime.h>
#include <cuda_bf16.h>
#include <cstdint>
#include <cstddef>

constexpr int S_BS = 8, S_SEQ = 512, S_DIM = 768, S_NP = 32, S_PE = 200;
constexpr int S_L = 20, S_EMB = 128, S_VOCAB = 30522;
constexpr int S_BP = S_BS * S_NP;            // 256
constexpr int S_ROWS = S_BP * S_L;           // 5120
constexpr int S_DIN2 = 2 * S_DIM;            // 1536

// ---------------- scratch ----------------
constexpr size_t SZ_A1   = (size_t)S_BP * S_DIN2 * 2;      // bf16
constexpr size_t SZ_W1T  = (size_t)S_DIM * S_DIN2 * 2;
constexpr size_t SZ_W2T  = (size_t)S_DIM * S_DIM * 2;
constexpr size_t SZ_WPT  = (size_t)S_EMB * S_DIM * 2;
constexpr size_t SZ_WD   = (size_t)S_VOCAB * S_EMB * 2;
constexpr size_t SZ_P    = (size_t)S_BP * S_DIM * 4;       // f32
constexpr size_t SZ_POSP = (size_t)S_L * S_DIM * 4;
constexpr size_t SZ_H1   = (size_t)S_ROWS * S_DIM * 2;
constexpr size_t SZ_PRE2 = (size_t)S_ROWS * S_DIM * 4;
constexpr size_t SZ_H3   = (size_t)S_ROWS * S_EMB * 2;

constexpr size_t OFF_A1H  = 0;
constexpr size_t OFF_A1L  = OFF_A1H  + SZ_A1;
constexpr size_t OFF_W1TH = OFF_A1L  + SZ_A1;
constexpr size_t OFF_W1TL = OFF_W1TH + SZ_W1T;
constexpr size_t OFF_W2TH = OFF_W1TL + SZ_W1T;
constexpr size_t OFF_W2TL = OFF_W2TH + SZ_W2T;
constexpr size_t OFF_WPTH = OFF_W2TL + SZ_W2T;
constexpr size_t OFF_WPTL = OFF_WPTH + SZ_WPT;
constexpr size_t OFF_WDH  = OFF_WPTL + SZ_WPT;
constexpr size_t OFF_WDL  = OFF_WDH  + SZ_WD;
constexpr size_t OFF_P    = OFF_WDL  + SZ_WD;
constexpr size_t OFF_POSP = OFF_P    + SZ_P;
constexpr size_t OFF_H1H  = OFF_POSP + SZ_POSP;
constexpr size_t OFF_H1L  = OFF_H1H  + SZ_H1;
constexpr size_t OFF_PRE2 = OFF_H1L  + SZ_H1;
constexpr size_t OFF_H2H  = OFF_PRE2 + SZ_PRE2;
constexpr size_t OFF_H2L  = OFF_H2H  + SZ_H1;
constexpr size_t OFF_H3H  = OFF_H2L  + SZ_H1;
constexpr size_t OFF_H3L  = OFF_H3H  + SZ_H3;
constexpr size_t SCRATCH_BYTES = OFF_H3L + SZ_H3;

__device__ __align__(1024) unsigned char g_scratch[SCRATCH_BYTES];

// ---------------- helpers ----------------
__device__ __forceinline__ void split2(float v, __nv_bfloat16& hi, __nv_bfloat16& lo) {
    __nv_bfloat16 h = __float2bfloat16(v);
    hi = h;
    lo = __float2bfloat16(v - __bfloat162float(h));
}

__device__ __forceinline__ float gelu_exact(float x) {
    return 0.5f * x * (1.0f + erff(x * 0.70710678118654752440f));
}

__device__ __forceinline__ uint32_t sm_u32(const void* p) {
    uint32_t a;
    asm("{ .reg .u64 t; cvta.to.shared.u64 t, %1; cvt.u32.u64 %0, t; }"
        : "=r"(a) : "l"(p));
    return a;
}

#define MMA_BF16(c, a, b)                                                     \
    asm volatile(                                                             \
        "mma.sync.aligned.m16n8k16.row.col.f32.bf16.bf16.f32 "                \
        "{%0,%1,%2,%3},{%4,%5,%6,%7},{%8,%9},{%0,%1,%2,%3};\n"                \
        : "+f"((c)[0]), "+f"((c)[1]), "+f"((c)[2]), "+f"((c)[3])              \
        : "r"((a)[0]), "r"((a)[1]), "r"((a)[2]), "r"((a)[3]),                 \
          "r"((b)[0]), "r"((b)[1]))

#define LDSM4(r, a)                                                           \
    asm volatile("ldmatrix.sync.aligned.m8n8.x4.shared.b16 "                  \
                 "{%0,%1,%2,%3}, [%4];"                                       \
                 : "=r"((r)[0]), "=r"((r)[1]), "=r"((r)[2]), "=r"((r)[3])     \
                 : "r"(a))

#define CP16(dst, src, sz)                                                    \
    asm volatile("cp.async.cg.shared.global [%0], [%1], 16, %2;\n"            \
                 :: "r"(dst), "l"(src), "r"(sz))

#define CP_COMMIT()  asm volatile("cp.async.commit_group;\n" ::: "memory")
#define CP_WAIT(n)   asm volatile("cp.async.wait_group %0;\n" :: "n"(n) : "memory")

__device__ __forceinline__ uint32_t swz(uint32_t off) {
    return off ^ ((off >> 3) & 0x70);
}

// ---------------- prep kernels ----------------
__global__ void gather_split_kernel(const float* __restrict__ hidden,
                                    const int* __restrict__ pairs,
                                    __nv_bfloat16* __restrict__ Ah,
                                    __nv_bfloat16* __restrict__ Al) {
    int id = blockIdx.x * 256 + threadIdx.x;      // 256*1536
    int bp = id / S_DIN2;
    int k  = id - bp * S_DIN2;
    int side = (k >= S_DIM) ? 1 : 0;
    int col  = k - side * S_DIM;
    int s = pairs[bp * 2 + side];
    int b = bp >> 5;
    float v = hidden[((size_t)(b * S_SEQ + s)) * S_DIM + col];
    split2(v, Ah[id], Al[id]);
}

__device__ void do_transpose32(const float* __restrict__ W, int K, int N,
                               __nv_bfloat16* __restrict__ Th,
                               __nv_bfloat16* __restrict__ Tl,
                               int tilex, int tiley) {
    __shared__ float tile[32][33];
    int t = threadIdx.x;
    int x = t & 31, y = t >> 5;
    int k0 = tiley * 32, n0 = tilex * 32;
    #pragma unroll
    for (int i = 0; i < 4; i++) {
        int kk = y + i * 8;
        tile[kk][x] = W[(size_t)(k0 + kk) * N + n0 + x];
    }
    __syncthreads();
    #pragma unroll
    for (int i = 0; i < 4; i++) {
        int nn = y + i * 8;
        float v = tile[x][nn];
        size_t o = (size_t)(n0 + nn) * K + k0 + x;
        split2(v, Th[o], Tl[o]);
    }
}

constexpr int WP_W1 = (S_DIM / 32) * (S_DIN2 / 32);         // 1152
constexpr int WP_W2 = WP_W1 + (S_DIM / 32) * (S_DIM / 32);  // 1728
constexpr int WP_WP = WP_W2 + (S_EMB / 32) * (S_DIM / 32);  // 1824
constexpr int WD_ELEMS = S_VOCAB * S_EMB;                    // 3906816
constexpr int WP_WD = WP_WP + (WD_ELEMS + 1023) / 1024;      // 5640

__global__ void weights_prep_kernel(const float* __restrict__ W1,
                                    const float* __restrict__ W2,
                                    const float* __restrict__ Wp,
                                    const float* __restrict__ Wdec,
                                    __nv_bfloat16* __restrict__ W1th, __nv_bfloat16* __restrict__ W1tl,
                                    __nv_bfloat16* __restrict__ W2th, __nv_bfloat16* __restrict__ W2tl,
                                    __nv_bfloat16* __restrict__ Wpth, __nv_bfloat16* __restrict__ Wptl,
                                    __nv_bfloat16* __restrict__ Wdh,  __nv_bfloat16* __restrict__ Wdl) {
    int bx = blockIdx.x;
    if (bx < WP_W1) {
        int tx = bx % (S_DIM / 32), ty = bx / (S_DIM / 32);
        do_transpose32(W1, S_DIN2, S_DIM, W1th, W1tl, tx, ty);
    } else if (bx < WP_W2) {
        int b = bx - WP_W1;
        int tx = b % (S_DIM / 32), ty = b / (S_DIM / 32);
        do_transpose32(W2, S_DIM, S_DIM, W2th, W2tl, tx, ty);
    } else if (bx < WP_WP) {
        int b = bx - WP_W2;
        int tx = b % (S_EMB / 32), ty = b / (S_EMB / 32);
        do_transpose32(Wp, S_DIM, S_EMB, Wpth, Wptl, tx, ty);
    } else {
        int base = (bx - WP_WP) * 1024;
        #pragma unroll
        for (int u = 0; u < 4; u++) {
            int id = base + threadIdx.x + u * 256;
            if (id < WD_ELEMS) split2(Wdec[id], Wdh[id], Wdl[id]);
        }
    }
}

__global__ void posmat_kernel(const float* __restrict__ pos_emb,
                              const float* __restrict__ W1,
                              float* __restrict__ PosP) {
    __shared__ float sp[S_PE];
    int l = blockIdx.x;
    if (threadIdx.x < S_PE) sp[threadIdx.x] = pos_emb[l * S_PE + threadIdx.x];
    __syncthreads();
    int n = threadIdx.x;
    float a = 0.f;
    #pragma unroll 4
    for (int k = 0; k < S_PE; k++)
        a += sp[k] * W1[(size_t)(S_DIN2 + k) * S_DIM + n];
    PosP[l * S_DIM + n] = a;
}

// ---------------- ldmatrix + mma compute for one 64-k chunk ----------------
// smem matrices: [row][128B] rows with SW128 swizzle (16B columns ^= row&7).
template<int MI>
__device__ __forceinline__ void chunk_mma(uint32_t sAh, uint32_t sAl,
                                          uint32_t sBh, uint32_t sBl,
                                          int m0, int n0, int lane,
                                          float acc[][4][4]) {
    #pragma unroll
    for (int ks = 0; ks < 4; ks++) {
        uint32_t ah[MI][4], al[MI][4], bh[8], bl[8];
        #pragma unroll
        for (int mi = 0; mi < MI; mi++) {
            int row = m0 + mi * 16 + (lane & 15);
            int c16 = ks * 2 + (lane >> 4);
            uint32_t off = swz((uint32_t)(row * 128 + c16 * 16));
            LDSM4(ah[mi], sAh + off);
            LDSM4(al[mi], sAl + off);
        }
        #pragma unroll
        for (int np = 0; np < 2; np++) {
            int row = n0 + np * 16 + ((lane >> 4) << 3) + (lane & 7);
            int c16 = ks * 2 + ((lane >> 3) & 1);
            uint32_t off = swz((uint32_t)(row * 128 + c16 * 16));
            LDSM4(&bh[np * 4], sBh + off);
            LDSM4(&bl[np * 4], sBl + off);
        }
        #pragma unroll
        for (int mi = 0; mi < MI; mi++)
            #pragma unroll
            for (int nj = 0; nj < 4; nj++) {
                MMA_BF16(acc[mi][nj], ah[mi], &bh[nj * 2]);
                MMA_BF16(acc[mi][nj], ah[mi], &bl[nj * 2]);
                MMA_BF16(acc[mi][nj], al[mi], &bh[nj * 2]);
            }
    }
}

// ---------------- k-loop GEMM: C[M,N] = A[M,K] @ Bt[N,K]^T (+bias) ----------
// Block tile (MI*32) x 128, chunk K=64, 2-stage cp.async, ldmatrix fragments.
// M % (MI*32) == 0, N % 128 == 0, K % 64 == 0.
template<int MI>
__global__ void __launch_bounds__(256)
gemm_kl(int M, int N, int K,
        const __nv_bfloat16* __restrict__ Ahp, const __nv_bfloat16* __restrict__ Alp,
        const __nv_bfloat16* __restrict__ Bhp, const __nv_bfloat16* __restrict__ Blp,
        const float* __restrict__ bias,
        float* __restrict__ Cf,
        __nv_bfloat16* __restrict__ Ch, __nv_bfloat16* __restrict__ Cl) {
    constexpr int MT = MI * 32;
    constexpr int AB = MT * 128;            // bytes per A matrix per stage
    constexpr int SS = 2 * AB + 32768;      // stage bytes
    extern __shared__ __align__(1024) unsigned char smraw[];
    const uint32_t smb = sm_u32(smraw);
    const int tid = threadIdx.x, lane = tid & 31, warp = tid >> 5;
    const int m0 = (warp >> 2) * MI * 16, n0 = (warp & 3) * 32;
    const int am0 = blockIdx.x * MT, bn0 = blockIdx.y * 128;
    const long rowB = (long)K * 2;
    const int nch = K >> 6;

    float acc[MI][4][4];
    #pragma unroll
    for (int a = 0; a < MI; a++)
        #pragma unroll
        for (int b = 0; b < 4; b++)
            #pragma unroll
            for (int c = 0; c < 4; c++) acc[a][b][c] = 0.f;

    auto load_stage = [&](int c, int s) {
        const uint32_t sb = smb + (uint32_t)s * SS;
        constexpr int AU = AB / 16;
        #pragma unroll
        for (int i = 0; i < (2 * AU) / 256; i++) {
            int u = tid + i * 256;
            int hi = (u >= AU); int v = u - hi * AU;
            int row = v >> 3, j = v & 7;
            uint32_t off = swz((uint32_t)(row * 128 + j * 16));
            const char* src = (hi ? (const char*)Alp : (const char*)Ahp)
                              + (long)(am0 + row) * rowB + (long)c * 128 + j * 16;
            CP16(sb + (uint32_t)hi * AB + off, src, 16);
        }
        #pragma unroll
        for (int i = 0; i < 8; i++) {
            int u = tid + i * 256;
            int hi = (u >= 1024); int v = u - hi * 1024;
            int row = v >> 3, j = v & 7;
            int grow = bn0 + row;
            int ok = (grow < N) ? 16 : 0;
            uint32_t off = swz((uint32_t)(row * 128 + j * 16));
            const char* src = (hi ? (const char*)Blp : (const char*)Bhp)
                              + (long)(ok ? grow : 0) * rowB + (long)c * 128 + j * 16;
            CP16(sb + 2u * AB + (uint32_t)hi * 16384u + off, src, ok);
        }
        CP_COMMIT();
    };

    load_stage(0, 0);
    for (int c = 0; c < nch; c++) {
        int s = c & 1;
        if (c + 1 < nch) { load_stage(c + 1, s ^ 1); CP_WAIT(1); }
        else             { CP_WAIT(0); }
        __syncthreads();
        uint32_t sb = smb + (uint32_t)s * SS;
        chunk_mma<MI>(sb, sb + AB, sb + 2 * AB, sb + 2 * AB + 16384,
                      m0, n0, lane, acc);
        __syncthreads();
    }

    const int g = lane >> 2, tg = lane & 3;
    #pragma unroll
    for (int mi = 0; mi < MI; mi++) {
        int r0 = am0 + m0 + mi * 16 + g;
        size_t base0 = (size_t)r0 * N;
        size_t base1 = (size_t)(r0 + 8) * N;
        #pragma unroll
        for (int nj = 0; nj < 4; nj++) {
            int c0 = bn0 + n0 + nj * 8 + tg * 2;
            float v0 = acc[mi][nj][0], v1 = acc[mi][nj][1];
            float v2 = acc[mi][nj][2], v3 = acc[mi][nj][3];
            if (bias) {
                float bb0 = bias[c0], bb1 = bias[c0 + 1];
                v0 += bb0; v1 += bb1; v2 += bb0; v3 += bb1;
            }
            if (Cf) {
                *(float2*)(Cf + base0 + c0) = make_float2(v0, v1);
                *(float2*)(Cf + base1 + c0) = make_float2(v2, v3);
            } else {
                split2(v0, Ch[base0 + c0],     Cl[base0 + c0]);
                split2(v1, Ch[base0 + c0 + 1], Cl[base0 + c0 + 1]);
                split2(v2, Ch[base1 + c0],     Cl[base1 + c0]);
                split2(v3, Ch[base1 + c0 + 1], Cl[base1 + c0 + 1]);
            }
        }
    }
}

// ---------------- persistent n-loop GEMM for GEMM4 (K=128 fixed) -----------
// A (hi/lo, full K=128) resident in smem; streams B n-tiles double-buffered.
// smem: A [chunk(2)][hi/lo][128x128B] = 64KB; B stages at 64KB + s*64KB.
constexpr int NL_SMEM = 196608;

__global__ void __launch_bounds__(256)
gemm_nl(int M, int N,
        const __nv_bfloat16* __restrict__ Ahp, const __nv_bfloat16* __restrict__ Alp,
        const __nv_bfloat16* __restrict__ Bhp, const __nv_bfloat16* __restrict__ Blp,
        float* __restrict__ Cf) {
    extern __shared__ __align__(1024) unsigned char smraw[];
    const uint32_t smb = sm_u32(smraw);
    const int tid = threadIdx.x, lane = tid & 31, warp = tid >> 5;
    const int m0 = (warp >> 2) * 64, n0 = (warp & 3) * 32;
    const int ntiles = (N + 127) >> 7;
    const int W = (M >> 7) * ntiles;
    const int Q = W / gridDim.x, R = W % gridDim.x;
    const int k = blockIdx.x;
    const int beg = k * Q + min(k, R);
    const int cnt = Q + (k < R ? 1 : 0);
    if (cnt == 0) return;

    auto load_A = [&](int m) {
        #pragma unroll
        for (int i = 0; i < 16; i++) {
            int u = tid + i * 256;            // [0,4096)
            int c = u >> 11; int v = u & 2047;
            int hi = v >> 10; int v2 = v & 1023;
            int row = v2 >> 3, j = v2 & 7;
            uint32_t off = swz((uint32_t)(row * 128 + j * 16));
            const char* src = (hi ? (const char*)Alp : (const char*)Ahp)
                              + (long)(m * 128 + row) * 256 + c * 128 + j * 16;
            CP16(smb + (uint32_t)c * 32768u + (uint32_t)hi * 16384u + off, src, 16);
        }
        CP_COMMIT();
    };
    auto load_B = [&](int n, int s) {
        #pragma unroll
        for (int i = 0; i < 16; i++) {
            int u = tid + i * 256;
            int c = u >> 11; int v = u & 2047;
            int hi = v >> 10; int v2 = v & 1023;
            int row = v2 >> 3, j = v2 & 7;
            int grow = n * 128 + row;
            int ok = (grow < N) ? 16 : 0;
            uint32_t off = swz((uint32_t)(row * 128 + j * 16));
            const char* src = (hi ? (const char*)Blp : (const char*)Bhp)
                              + (long)(ok ? grow : 0) * 256 + c * 128 + j * 16;
            CP16(smb + 65536u + (uint32_t)s * 65536u
                 + (uint32_t)c * 32768u + (uint32_t)hi * 16384u + off, src, ok);
        }
        CP_COMMIT();
    };

    int loadedm = beg / ntiles;
    load_A(loadedm);
    load_B(beg % ntiles, 0);

    const int g = lane >> 2, tg = lane & 3;
    for (int it = 0; it < cnt; it++) {
        int w = beg + it, s = it & 1;
        int mm = w / ntiles, nn = w % ntiles;
        if (mm != loadedm) { load_A(mm); loadedm = mm; }
        if (it + 1 < cnt) {
            int wn = w + 1;
            load_B(wn % ntiles, s ^ 1);
            CP_WAIT(1);
        } else {
            CP_WAIT(0);
        }
        __syncthreads();

        float acc[4][4][4];
        #pragma unroll
        for (int a = 0; a < 4; a++)
            #pragma unroll
            for (int b = 0; b < 4; b++)
                #pragma unroll
                for (int c = 0; c < 4; c++) acc[a][b][c] = 0.f;

        uint32_t bB = smb + 65536u + (uint32_t)s * 65536u;
        #pragma unroll
        for (int c = 0; c < 2; c++) {
            uint32_t aoff = smb + (uint32_t)c * 32768u;
            uint32_t boff = bB + (uint32_t)c * 32768u;
            chunk_mma<4>(aoff, aoff + 16384u, boff, boff + 16384u,
                         m0, n0, lane, acc);
        }

        // epilogue
        #pragma unroll
        for (int mi = 0; mi < 4; mi++) {
            int r0 = mm * 128 + m0 + mi * 16 + g;
            size_t base0 = (size_t)r0 * N;
            size_t base1 = (size_t)(r0 + 8) * N;
            #pragma unroll
            for (int nj = 0; nj < 4; nj++) {
                int c0 = nn * 128 + n0 + nj * 8 + tg * 2;
                if (c0 + 1 < N) {
                    *(float2*)(Cf + base0 + c0) =
                        make_float2(acc[mi][nj][0], acc[mi][nj][1]);
                    *(float2*)(Cf + base1 + c0) =
                        make_float2(acc[mi][nj][2], acc[mi][nj][3]);
                } else if (c0 < N) {
                    Cf[base0 + c0] = acc[mi][nj][0];
                    Cf[base1 + c0] = acc[mi][nj][2];
                }
            }
        }
        __syncthreads();
    }
}

// ---------------- gelu + LN (one 768-row per 256-thread block) ----------------
__device__ __forceinline__ void ln_write(float v0, float v1, float v2, int r,
                                         const float* __restrict__ gam,
                                         const float* __restrict__ bet,
                                         __nv_bfloat16* __restrict__ Hh,
                                         __nv_bfloat16* __restrict__ Hl,
                                         float* red) {
    int t = threadIdx.x;
    float s1 = v0 + v1 + v2;
    float s2 = v0 * v0 + v1 * v1 + v2 * v2;
    #pragma unroll
    for (int o = 16; o; o >>= 1) {
        s1 += __shfl_xor_sync(0xffffffffu, s1, o);
        s2 += __shfl_xor_sync(0xffffffffu, s2, o);
    }
    if ((t & 31) == 0) { red[t >> 5] = s1; red[8 + (t >> 5)] = s2; }
    __syncthreads();
    s1 = 0.f; s2 = 0.f;
    #pragma unroll
    for (int i = 0; i < 8; i++) { s1 += red[i]; s2 += red[8 + i]; }
    float mean = s1 * (1.0f / S_DIM);
    float var  = s2 * (1.0f / S_DIM) - mean * mean;
    float rstd = rsqrtf(fmaxf(var, 0.0f) + 1e-12f);
    size_t rb = (size_t)r * S_DIM;
    float v[3] = {v0, v1, v2};
    #pragma unroll
    for (int j = 0; j < 3; j++) {
        int c = t + j * 256;
        float y = (v[j] - mean) * rstd * gam[c] + bet[c];
        split2(y, Hh[rb + c], Hl[rb + c]);
    }
}

__global__ void expand_act_kernel(const float* __restrict__ P,
                                  const float* __restrict__ PosP,
                                  const float* __restrict__ b1,
                                  const float* __restrict__ g1,
                                  const float* __restrict__ be1,
                                  __nv_bfloat16* __restrict__ Hh,
                                  __nv_bfloat16* __restrict__ Hl) {
    __shared__ float red[16];
    int r = blockIdx.x;
    int bp = r / S_L, l = r - bp * S_L;
    int t = threadIdx.x;
    float v[3];
    #pragma unroll
    for (int j = 0; j < 3; j++) {
        int c = t + j * 256;
        float pre = P[bp * S_DIM + c] + PosP[l * S_DIM + c] + b1[c];
        v[j] = gelu_exact(pre);
    }
    ln_write(v[0], v[1], v[2], r, g1, be1, Hh, Hl, red);
}

__global__ void act2_kernel(const float* __restrict__ X,
                            const float* __restrict__ g2,
                            const float* __restrict__ be2,
                            __nv_bfloat16* __restrict__ Hh,
                            __nv_bfloat16* __restrict__ Hl) {
    __shared__ float red[16];
    int r = blockIdx.x;
    int t = threadIdx.x;
    size_t rb = (size_t)r * S_DIM;
    float v[3];
    #pragma unroll
    for (int j = 0; j < 3; j++) {
        int c = t + j * 256;
        v[j] = gelu_exact(X[rb + c]);
    }
    ln_write(v[0], v[1], v[2], r, g2, be2, Hh, Hl, red);
}

// ---------------- launch ----------------
extern "C" void kernel_launch(void* const* d_in, const int* in_sizes, int n_in,
                              void* d_out, int out_size) {
    (void)in_sizes; (void)n_in; (void)out_size;
    const float* hidden  = (const float*)d_in[0];
    const int*   pairs   = (const int*)d_in[1];
    const float* pos_emb = (const float*)d_in[2];
    const float* W1      = (const float*)d_in[3];
    const float* b1      = (const float*)d_in[4];
    const float* g1      = (const float*)d_in[5];
    const float* be1     = (const float*)d_in[6];
    const float* W2      = (const float*)d_in[7];
    const float* b2      = (const float*)d_in[8];
    const float* g2      = (const float*)d_in[9];
    const float* be2     = (const float*)d_in[10];
    const float* Wp      = (const float*)d_in[11];
    const float* bpv     = (const float*)d_in[12];
    const float* Wdec    = (const float*)d_in[13];
    float* out = (float*)d_out;

    void* sp = nullptr;
    cudaGetSymbolAddress(&sp, g_scratch);
    char* S = (char*)sp;
    __nv_bfloat16* A1h  = (__nv_bfloat16*)(S + OFF_A1H);
    __nv_bfloat16* A1l  = (__nv_bfloat16*)(S + OFF_A1L);
    __nv_bfloat16* W1th = (__nv_bfloat16*)(S + OFF_W1TH);
    __nv_bfloat16* W1tl = (__nv_bfloat16*)(S + OFF_W1TL);
    __nv_bfloat16* W2th = (__nv_bfloat16*)(S + OFF_W2TH);
    __nv_bfloat16* W2tl = (__nv_bfloat16*)(S + OFF_W2TL);
    __nv_bfloat16* Wpth = (__nv_bfloat16*)(S + OFF_WPTH);
    __nv_bfloat16* Wptl = (__nv_bfloat16*)(S + OFF_WPTL);
    __nv_bfloat16* Wdh  = (__nv_bfloat16*)(S + OFF_WDH);
    __nv_bfloat16* Wdl  = (__nv_bfloat16*)(S + OFF_WDL);
    float* P    = (float*)(S + OFF_P);
    float* PosP = (float*)(S + OFF_POSP);
    __nv_bfloat16* h1h = (__nv_bfloat16*)(S + OFF_H1H);
    __nv_bfloat16* h1l = (__nv_bfloat16*)(S + OFF_H1L);
    float* pre2 = (float*)(S + OFF_PRE2);
    __nv_bfloat16* h2h = (__nv_bfloat16*)(S + OFF_H2H);
    __nv_bfloat16* h2l = (__nv_bfloat16*)(S + OFF_H2L);
    __nv_bfloat16* h3h = (__nv_bfloat16*)(S + OFF_H3H);
    __nv_bfloat16* h3l = (__nv_bfloat16*)(S + OFF_H3L);

    constexpr int SM2 = 2 * (2 * 64 * 128 + 32768);   // MI=2 stages: 98304
    cudaFuncSetAttribute(gemm_kl<2>,
                         cudaFuncAttributeMaxDynamicSharedMemorySize, SM2);
    cudaFuncSetAttribute(gemm_nl,
                         cudaFuncAttributeMaxDynamicSharedMemorySize, NL_SMEM);

    // 1: gather endpoints
    gather_split_kernel<<<(S_BP * S_DIN2) / 256, 256>>>(hidden, pairs, A1h, A1l);
    // 2: all weight prep
    weights_prep_kernel<<<WP_WD, 256>>>(W1, W2, Wp, Wdec,
                                        W1th, W1tl, W2th, W2tl,
                                        Wpth, Wptl, Wdh, Wdl);
    // 3: pos-embedding projection
    posmat_kernel<<<S_L, S_DIM>>>(pos_emb, W1, PosP);

    // 4: GEMM1  P[256,768] = Acat[256,1536] @ W1t^T
    gemm_kl<2><<<dim3(S_BP / 64, S_DIM / 128), 256, SM2>>>(
        S_BP, S_DIM, S_DIN2, A1h, A1l, W1th, W1tl,
        nullptr, P, nullptr, nullptr);

    // 5: expand over L + gelu + LN1 -> h1
    expand_act_kernel<<<S_ROWS, 256>>>(P, PosP, b1, g1, be1, h1h, h1l);

    // 6: GEMM2  pre2[5120,768] = h1 @ W2t^T + b2   (ncu captures this one)
    gemm_kl<2><<<dim3(S_ROWS / 64, S_DIM / 128), 256, SM2>>>(
        S_ROWS, S_DIM, S_DIM, h1h, h1l, W2th, W2tl,
        b2, pre2, nullptr, nullptr);

    // 7: gelu + LN2 -> h2
    act2_kernel<<<S_ROWS, 256>>>(pre2, g2, be2, h2h, h2l);

    // 8: GEMM3  h3[5120,128] = h2 @ Wpt^T + bp
    gemm_kl<2><<<dim3(S_ROWS / 64, 1), 256, SM2>>>(
        S_ROWS, S_EMB, S_DIM, h2h, h2l, Wpth, Wptl,
        bpv, nullptr, h3h, h3l);

    // 9: GEMM4  out[5120,30522] = h3 @ Wdec^T  (persistent, A-resident)
    gemm_nl<<<148, 256, NL_SMEM>>>(
        S_ROWS, S_VOCAB, h3h, h3l, Wdh, Wdl, out);
}